// round 6
// baseline (speedup 1.0000x reference)
#include <cuda_runtime.h>
#include <math.h>

#define N_NODES 50000
#define B 64
#define M 32
#define E 128
#define H 8
#define TILE 64
#define WPAD 132

// scratch (allocation-free rule: __device__ globals)
__device__ float g_wv_accum[B * E];
__device__ float g_att2[B * M * H];
__device__ float g_pre[(size_t)N_NODES * E];   // einsum result, pre-Wo

// ---------------------------------------------------------------------------
// K0: zero accumulator + att2[b][m][h] = mv[b,m,:]@Wa2 + ba2  (exact fp32)
// ---------------------------------------------------------------------------
__global__ void k0_init(const float* __restrict__ mv,
                        const float* __restrict__ Wa2,
                        const float* __restrict__ ba2) {
    int t = blockIdx.x * blockDim.x + threadIdx.x;
    if (t < B * E) g_wv_accum[t] = 0.f;
    if (t < B * M) {
        int b = t >> 5, m = t & 31;
        float acc[H];
#pragma unroll
        for (int h = 0; h < H; h++) acc[h] = 0.f;
        const float* row = mv + (size_t)(b * M + m) * E;
        for (int e = 0; e < E; e++) {
            float v = row[e];
#pragma unroll
            for (int h = 0; h < H; h++) acc[h] += v * Wa2[e * H + h];
        }
#pragma unroll
        for (int h = 0; h < H; h++) g_att2[t * H + h] = acc[h] + ba2[h];
    }
}

// ---------------------------------------------------------------------------
// KW: wv = z@Wv + bv, segment-sum into g_wv_accum (tile kernel, proven shape)
// ---------------------------------------------------------------------------
__global__ void __launch_bounds__(256, 1)
kW_write(const float* __restrict__ z, const int* __restrict__ batch,
         const float* __restrict__ Wv, const float* __restrict__ bv) {
    extern __shared__ float sm[];
    float* WT = sm;                    // [128][WPAD]
    float* zs = WT + 128 * WPAD;       // [64][128]
    int* bats = (int*)(zs + TILE * E); // [64]

    const int tid = threadIdx.x;
    const int tilebase = blockIdx.x * TILE;
    const int nvalid = min(TILE, N_NODES - tilebase);

    for (int i = tid; i < E * E; i += 256) {
        int k = i >> 7, c = i & 127;
        WT[c * WPAD + k] = Wv[i];
    }
    for (int i4 = tid; i4 < TILE * E / 4; i4 += 256) {
        int n = i4 >> 5;
        float4 v = make_float4(0.f, 0.f, 0.f, 0.f);
        if (n < nvalid) v = ((const float4*)z)[(size_t)(tilebase + n) * 32 + (i4 & 31)];
        ((float4*)zs)[i4] = v;
    }
    if (tid < TILE) bats[tid] = (tid < nvalid) ? batch[tilebase + tid] : 0;
    __syncthreads();

    const int c  = tid & 127;
    const int nb = (tid >> 7) * 32;
    float acc[32];
    float bvc = bv[c];
#pragma unroll
    for (int j = 0; j < 32; j++) acc[j] = bvc;
    for (int k = 0; k < E; k += 4) {
        float4 w4 = *(const float4*)(WT + c * WPAD + k);
#pragma unroll
        for (int j = 0; j < 32; j++) {
            float4 z4 = *(const float4*)(zs + (nb + j) * E + k);
            acc[j] += z4.x * w4.x + z4.y * w4.y + z4.z * w4.z + z4.w * w4.w;
        }
    }
    int curg = -1;
    float run = 0.f;
#pragma unroll
    for (int j = 0; j < 32; j++) {
        int node = nb + j;
        int g = (node < nvalid) ? bats[node] : -2;
        if (g != curg) {
            if (curg >= 0) atomicAdd(&g_wv_accum[curg * E + c], run);
            curg = g;
            run = 0.f;
        }
        if (g >= 0) run += acc[j];
    }
    if (curg >= 0) atomicAdd(&g_wv_accum[curg * E + c], run);
}

// ---------------------------------------------------------------------------
// KA (diagnostic): one thread per node. Literal transcription of the reference
// attention math, exact fp32, precise expf, straight from global memory.
//   g_pre[n,:] = einsum result (pre-Wo)
// ---------------------------------------------------------------------------
__global__ void kA_attention(const float* __restrict__ z,
                             const int* __restrict__ batch,
                             const float* __restrict__ bias_mask,
                             const float* __restrict__ mv,
                             const float* __restrict__ Wa1,
                             const float* __restrict__ ba1,
                             const float* __restrict__ Wh,
                             const float* __restrict__ bh) {
    int n = blockIdx.x * blockDim.x + threadIdx.x;
    if (n >= N_NODES) return;
    int g = batch[n];

    // att1 = z[n] @ Wa1 + ba1
    float a1[H];
#pragma unroll
    for (int h = 0; h < H; h++) a1[h] = 0.f;
    const float* zr = z + (size_t)n * E;
    for (int k = 0; k < E; k++) {
        float zv = zr[k];
#pragma unroll
        for (int h = 0; h < H; h++) a1[h] += zv * Wa1[k * H + h];
    }
#pragma unroll
    for (int h = 0; h < H; h++) a1[h] += ba1[h];

    // per-slot bias
    float biasm[M];
#pragma unroll 8
    for (int m = 0; m < M; m++)
        biasm[m] = (bias_mask[g * M + m] - 1.0f) * 1e9f;

    // heads: softmax over slots, aggregate with Wh
    float w[M];
    float bh0 = bh[0];
#pragma unroll 8
    for (int m = 0; m < M; m++) w[m] = bh0;
    const float* a2 = g_att2 + g * M * H;
    for (int h = 0; h < H; h++) {
        float lh[M];
        float mx = -3.4e38f;
#pragma unroll 8
        for (int m = 0; m < M; m++) {
            float l = a1[h] + a2[m * H + h];
            l = (l >= 0.f) ? l : 0.01f * l;     // leaky_relu
            l = l + biasm[m];
            lh[m] = l;
            mx = fmaxf(mx, l);
        }
        float s = 0.f;
#pragma unroll 8
        for (int m = 0; m < M; m++) { lh[m] = expf(lh[m] - mx); s += lh[m]; }
        float whh = Wh[h];
#pragma unroll 8
        for (int m = 0; m < M; m++) w[m] += (lh[m] / s) * whh;
    }

    // second softmax over slots
    float mx2 = -3.4e38f;
#pragma unroll 8
    for (int m = 0; m < M; m++) mx2 = fmaxf(mx2, w[m]);
    float s2 = 0.f;
#pragma unroll 8
    for (int m = 0; m < M; m++) { w[m] = expf(w[m] - mx2); s2 += w[m]; }
#pragma unroll 8
    for (int m = 0; m < M; m++) w[m] = w[m] / s2;

    // einsum: pre[e] = sum_m w[m] * mv[g, m, e]
    const float* mvg = mv + (size_t)g * M * E;
    float* pre = g_pre + (size_t)n * E;
    for (int e = 0; e < E; e += 4) {
        float acc0 = 0.f, acc1 = 0.f, acc2 = 0.f, acc3 = 0.f;
#pragma unroll 8
        for (int m = 0; m < M; m++) {
            float cm = w[m];
            const float* r = mvg + m * E + e;
            acc0 += cm * r[0];
            acc1 += cm * r[1];
            acc2 += cm * r[2];
            acc3 += cm * r[3];
        }
        pre[e + 0] = acc0; pre[e + 1] = acc1; pre[e + 2] = acc2; pre[e + 3] = acc3;
    }
}

// ---------------------------------------------------------------------------
// KB (diagnostic): out0 = g_pre @ Wo + bo, one thread per (n, c)
// ---------------------------------------------------------------------------
__global__ void kB_wo(const float* __restrict__ Wo,
                      const float* __restrict__ bo,
                      float* __restrict__ out) {
    size_t idx = (size_t)blockIdx.x * blockDim.x + threadIdx.x;
    if (idx >= (size_t)N_NODES * E) return;
    int n = (int)(idx >> 7);
    int c = (int)(idx & 127);
    const float* pre = g_pre + (size_t)n * E;
    float acc = 0.f;
#pragma unroll 16
    for (int k = 0; k < E; k++) acc += pre[k] * Wo[k * E + c];
    out[idx] = acc + bo[c];
}

// ---------------------------------------------------------------------------
// K2: state updates + arange
// out layout: [output N*E | arange N | new_mv B*M*E | new_write_mask | new_bias_mask]
// ---------------------------------------------------------------------------
__global__ void k2_final(const float* __restrict__ mv,
                         const float* __restrict__ write_mask,
                         const float* __restrict__ bias_mask,
                         float* __restrict__ out) {
    int idx = blockIdx.x * blockDim.x + threadIdx.x;
    const size_t OUT1 = (size_t)N_NODES * E;
    const size_t OUT2 = OUT1 + N_NODES;
    const size_t OUT3 = OUT2 + (size_t)B * M * E;
    const size_t OUT4 = OUT3 + (size_t)B * M;
    if (idx < B * M * E) {
        int b = idx >> 12;
        int m = (idx >> 7) & 31;
        float wvv = tanhf(g_wv_accum[b * E + (idx & 127)]);
        out[OUT2 + idx] = mv[idx] + wvv * write_mask[b * M + m];
    }
    if (idx < B * M) {
        int b = idx >> 5, m = idx & 31;
        out[OUT3 + idx] = write_mask[b * M + ((m + 31) & 31)];
        out[OUT4 + idx] = fminf(bias_mask[idx] + write_mask[idx], 1.f);
    }
    if (idx < N_NODES) out[OUT1 + idx] = (float)idx;
}

// ---------------------------------------------------------------------------
extern "C" void kernel_launch(void* const* d_in, const int* in_sizes, int n_in,
                              void* d_out, int out_size) {
    const float* z     = (const float*)d_in[0];
    const int*   batch = (const int*)d_in[1];
    const float* mv    = (const float*)d_in[2];
    const float* wm    = (const float*)d_in[3];
    const float* bm    = (const float*)d_in[4];
    const float* Wv    = (const float*)d_in[5];
    const float* bv    = (const float*)d_in[6];
    const float* Wo    = (const float*)d_in[7];
    const float* bo    = (const float*)d_in[8];
    const float* Wa1   = (const float*)d_in[9];
    const float* ba1   = (const float*)d_in[10];
    const float* Wa2   = (const float*)d_in[11];
    const float* ba2   = (const float*)d_in[12];
    const float* Wh    = (const float*)d_in[13];
    const float* bh    = (const float*)d_in[14];
    float* out = (float*)d_out;

    const int SMEM_W = (128 * WPAD + TILE * E + TILE) * 4;
    cudaFuncSetAttribute(kW_write, cudaFuncAttributeMaxDynamicSharedMemorySize, SMEM_W);

    k0_init<<<32, 256>>>(mv, Wa2, ba2);

    int nblocks = (N_NODES + TILE - 1) / TILE;
    kW_write<<<nblocks, 256, SMEM_W>>>(z, batch, Wv, bv);

    kA_attention<<<(N_NODES + 127) / 128, 128>>>(z, batch, bm, mv, Wa1, ba1, Wh, bh);

    size_t total = (size_t)N_NODES * E;
    kB_wo<<<(int)((total + 255) / 256), 256>>>(Wo, bo, out);

    k2_final<<<(B * M * E + 255) / 256, 256>>>(mv, wm, bm, out);
}

// round 7
// speedup vs baseline: 1.3933x; 1.3933x over previous
#include <cuda_runtime.h>
#include <math.h>

#define N_NODES 50000
#define B 64
#define M 32
#define E 128
#define H 8
#define TILE 64
#define WPAD 132   // weight row pad: multiple of 4 -> float4-aligned rows

// scratch (allocation-free rule: __device__ globals)
__device__ float g_wv_accum[B * E];
__device__ float g_att2[B * M * H];

// ---------------------------------------------------------------------------
// K0: zero accumulator + att2[b][m][h] = mv[b,m,:]@Wa2 + ba2  (exact fp32)
// ---------------------------------------------------------------------------
__global__ void k0_init(const float* __restrict__ mv,
                        const float* __restrict__ Wa2,
                        const float* __restrict__ ba2) {
    int t = blockIdx.x * blockDim.x + threadIdx.x;
    if (t < B * E) g_wv_accum[t] = 0.f;
    if (t < B * M) {
        int b = t >> 5, m = t & 31;
        float acc[H];
#pragma unroll
        for (int h = 0; h < H; h++) acc[h] = 0.f;
        const float* row = mv + (size_t)(b * M + m) * E;
        for (int e = 0; e < E; e++) {
            float v = row[e];
#pragma unroll
            for (int h = 0; h < H; h++) acc[h] += v * Wa2[e * H + h];
        }
#pragma unroll
        for (int h = 0; h < H; h++) g_att2[t * H + h] = acc[h] + ba2[h];
    }
}

// ---------------------------------------------------------------------------
// K1: fused per-tile kernel. 64 nodes/block, 256 threads. Exact fp32.
// ---------------------------------------------------------------------------
__global__ void __launch_bounds__(256, 1)
k1_main(const float* __restrict__ z, const int* __restrict__ batch,
        const float* __restrict__ mv, const float* __restrict__ bias_mask,
        const float* __restrict__ Wv, const float* __restrict__ bv,
        const float* __restrict__ Wo, const float* __restrict__ bo,
        const float* __restrict__ Wa1, const float* __restrict__ ba1,
        const float* __restrict__ Wh, const float* __restrict__ bh,
        float* __restrict__ out) {
    extern __shared__ float sm[];
    float* WT   = sm;                   // [128][WPAD] transposed weight (Wv then Wo)
    float* zs   = WT + 128 * WPAD;      // [64][128] z tile, later output_pre
    float* att1 = zs + TILE * E;        // [64][8]
    float* cofs = att1 + TILE * H;      // [64][32]
    float* Wa1s = cofs + TILE * M;      // [128][8]
    int*   bats = (int*)(Wa1s + E * H); // [64]

    const int tid = threadIdx.x;
    const int tilebase = blockIdx.x * TILE;
    const int nvalid = min(TILE, N_NODES - tilebase);

    // --- cooperative loads (exact fp32) ---
    for (int i = tid; i < E * E; i += 256) {          // Wv -> WT (transposed)
        int k = i >> 7, c = i & 127;
        WT[c * WPAD + k] = Wv[i];
    }
    for (int i4 = tid; i4 < TILE * E / 4; i4 += 256) { // z tile (zero-fill tail)
        int n = i4 >> 5;
        float4 v = make_float4(0.f, 0.f, 0.f, 0.f);
        if (n < nvalid) v = ((const float4*)z)[(size_t)(tilebase + n) * 32 + (i4 & 31)];
        ((float4*)zs)[i4] = v;
    }
    for (int i = tid; i < E * H; i += 256) Wa1s[i] = Wa1[i];   // FIXED: full load
    if (tid < TILE) bats[tid] = (tid < nvalid) ? batch[tilebase + tid] : 0;
    __syncthreads();

    // --- att1 = z @ Wa1 + ba1 ---
    for (int p = tid; p < TILE * H; p += 256) {
        int n = p >> 3, h = p & 7;
        float s = 0.f;
        const float* zr = zs + n * E;
#pragma unroll 4
        for (int k = 0; k < E; k++) s += zr[k] * Wa1s[k * H + h];
        att1[p] = s + ba1[h];
    }

    // --- wv GEMM + segment accumulation ---
    const int c  = tid & 127;
    const int nh = tid >> 7;
    const int nb = nh * 32;
    {
        float acc[32];
        float bvc = bv[c];
#pragma unroll
        for (int j = 0; j < 32; j++) acc[j] = bvc;
        for (int k = 0; k < E; k += 4) {
            float4 w4 = *(const float4*)(WT + c * WPAD + k);
#pragma unroll
            for (int j = 0; j < 32; j++) {
                float4 z4 = *(const float4*)(zs + (nb + j) * E + k);
                acc[j] += z4.x * w4.x + z4.y * w4.y + z4.z * w4.z + z4.w * w4.w;
            }
        }
        int curg = -1;
        float run = 0.f;
#pragma unroll
        for (int j = 0; j < 32; j++) {
            int node = nb + j;
            int g = (node < nvalid) ? bats[node] : -2;
            if (g != curg) {
                if (curg >= 0) atomicAdd(&g_wv_accum[curg * E + c], run);
                curg = g;
                run = 0.f;
            }
            if (g >= 0) run += acc[j];
        }
        if (curg >= 0) atomicAdd(&g_wv_accum[curg * E + c], run);
    }
    __syncthreads();

    // --- load Wo -> WT (overwrite) ---
    for (int i = tid; i < E * E; i += 256) {
        int k = i >> 7, cc = i & 127;
        WT[cc * WPAD + k] = Wo[i];
    }

    // --- attention: 4 threads per node (exact fp32) ---
    {
        const int nl = tid >> 2, q = tid & 3;
        const int g = bats[nl];
        float a1[H];
#pragma unroll
        for (int h = 0; h < H; h++) a1[h] = att1[nl * H + h];
        float biasv[8];
#pragma unroll
        for (int mi = 0; mi < 8; mi++)
            biasv[mi] = (bias_mask[g * M + q * 8 + mi] - 1.f) * 1e9f;
        float w[8];
        float bh0 = bh[0];
#pragma unroll
        for (int mi = 0; mi < 8; mi++) w[mi] = bh0;
        const float* a2 = g_att2 + g * M * H;
#pragma unroll
        for (int h = 0; h < H; h++) {
            float lh[8];
            float mx = -3.4e38f;
#pragma unroll
            for (int mi = 0; mi < 8; mi++) {
                float l = a1[h] + a2[(q * 8 + mi) * H + h];
                l = (l >= 0.f) ? l : 0.01f * l;   // leaky_relu
                l += biasv[mi];
                lh[mi] = l;
                mx = fmaxf(mx, l);
            }
            mx = fmaxf(mx, __shfl_xor_sync(0xffffffffu, mx, 1));
            mx = fmaxf(mx, __shfl_xor_sync(0xffffffffu, mx, 2));
            float s = 0.f;
#pragma unroll
            for (int mi = 0; mi < 8; mi++) { lh[mi] = __expf(lh[mi] - mx); s += lh[mi]; }
            s += __shfl_xor_sync(0xffffffffu, s, 1);
            s += __shfl_xor_sync(0xffffffffu, s, 2);
            float whh = Wh[h];
            float invs = 1.f / s;
#pragma unroll
            for (int mi = 0; mi < 8; mi++) w[mi] += (lh[mi] * invs) * whh;
        }
        // second softmax over slots
        float mx2 = -3.4e38f;
#pragma unroll
        for (int mi = 0; mi < 8; mi++) mx2 = fmaxf(mx2, w[mi]);
        mx2 = fmaxf(mx2, __shfl_xor_sync(0xffffffffu, mx2, 1));
        mx2 = fmaxf(mx2, __shfl_xor_sync(0xffffffffu, mx2, 2));
        float s2 = 0.f;
#pragma unroll
        for (int mi = 0; mi < 8; mi++) { w[mi] = __expf(w[mi] - mx2); s2 += w[mi]; }
        s2 += __shfl_xor_sync(0xffffffffu, s2, 1);
        s2 += __shfl_xor_sync(0xffffffffu, s2, 2);
        float inv2 = 1.f / s2;
#pragma unroll
        for (int mi = 0; mi < 8; mi++) cofs[nl * M + q * 8 + mi] = w[mi] * inv2;
        __syncwarp();

        // output_pre = coefs @ mv[g]  (this thread owns e-chunk q*32..q*32+31)
        float op[32];
#pragma unroll
        for (int i = 0; i < 32; i++) op[i] = 0.f;
        const float4* mvg = (const float4*)(mv + (size_t)g * M * E) + q * 8;
#pragma unroll 4
        for (int m = 0; m < M; m++) {
            float cm = cofs[nl * M + m];
            const float4* row = mvg + m * 32;
#pragma unroll
            for (int i = 0; i < 8; i++) {
                float4 v = row[i];
                op[i * 4 + 0] += cm * v.x;
                op[i * 4 + 1] += cm * v.y;
                op[i * 4 + 2] += cm * v.z;
                op[i * 4 + 3] += cm * v.w;
            }
        }
        float4* zr = (float4*)(zs + nl * E + q * 32);
#pragma unroll
        for (int i = 0; i < 8; i++)
            zr[i] = make_float4(op[i * 4], op[i * 4 + 1], op[i * 4 + 2], op[i * 4 + 3]);
    }
    __syncthreads();

    // --- out = output_pre @ Wo + bo ---
    {
        float acc2[32];
        float boc = bo[c];
#pragma unroll
        for (int j = 0; j < 32; j++) acc2[j] = boc;
        for (int k = 0; k < E; k += 4) {
            float4 w4 = *(const float4*)(WT + c * WPAD + k);
#pragma unroll
            for (int j = 0; j < 32; j++) {
                float4 z4 = *(const float4*)(zs + (nb + j) * E + k);
                acc2[j] += z4.x * w4.x + z4.y * w4.y + z4.z * w4.z + z4.w * w4.w;
            }
        }
#pragma unroll
        for (int j = 0; j < 32; j++) {
            if (nb + j < nvalid)
                out[(size_t)(tilebase + nb + j) * E + c] = acc2[j];
        }
    }
}

// ---------------------------------------------------------------------------
// K2: state updates + arange output
// out layout: [output N*E | arange N | new_mv B*M*E | new_write_mask | new_bias_mask]
// ---------------------------------------------------------------------------
__global__ void k2_final(const float* __restrict__ mv,
                         const float* __restrict__ write_mask,
                         const float* __restrict__ bias_mask,
                         float* __restrict__ out) {
    int idx = blockIdx.x * blockDim.x + threadIdx.x;
    const size_t OUT1 = (size_t)N_NODES * E;
    const size_t OUT2 = OUT1 + N_NODES;
    const size_t OUT3 = OUT2 + (size_t)B * M * E;
    const size_t OUT4 = OUT3 + (size_t)B * M;
    if (idx < B * M * E) {
        int b = idx >> 12;
        int m = (idx >> 7) & 31;
        float wvv = tanhf(g_wv_accum[b * E + (idx & 127)]);
        out[OUT2 + idx] = mv[idx] + wvv * write_mask[b * M + m];
    }
    if (idx < B * M) {
        int b = idx >> 5, m = idx & 31;
        out[OUT3 + idx] = write_mask[b * M + ((m + 31) & 31)];        // roll(+1)
        out[OUT4 + idx] = fminf(bias_mask[idx] + write_mask[idx], 1.f);
    }
    if (idx < N_NODES) out[OUT1 + idx] = (float)idx;                  // arange
}

// ---------------------------------------------------------------------------
extern "C" void kernel_launch(void* const* d_in, const int* in_sizes, int n_in,
                              void* d_out, int out_size) {
    const float* z     = (const float*)d_in[0];
    const int*   batch = (const int*)d_in[1];
    const float* mv    = (const float*)d_in[2];
    const float* wm    = (const float*)d_in[3];
    const float* bm    = (const float*)d_in[4];
    const float* Wv    = (const float*)d_in[5];
    const float* bv    = (const float*)d_in[6];
    const float* Wo    = (const float*)d_in[7];
    const float* bo    = (const float*)d_in[8];
    const float* Wa1   = (const float*)d_in[9];
    const float* ba1   = (const float*)d_in[10];
    const float* Wa2   = (const float*)d_in[11];
    const float* ba2   = (const float*)d_in[12];
    const float* Wh    = (const float*)d_in[13];
    const float* bh    = (const float*)d_in[14];
    float* out = (float*)d_out;

    const int SMEM_BYTES =
        (128 * WPAD + TILE * E + TILE * H + TILE * M + E * H + TILE) * 4;
    cudaFuncSetAttribute(k1_main, cudaFuncAttributeMaxDynamicSharedMemorySize,
                         SMEM_BYTES);

    k0_init<<<32, 256>>>(mv, Wa2, ba2);

    int nblocks = (N_NODES + TILE - 1) / TILE;
    k1_main<<<nblocks, 256, SMEM_BYTES>>>(z, batch, mv, bm, Wv, bv, Wo, bo,
                                          Wa1, ba1, Wh, bh, out);

    k2_final<<<(B * M * E + 255) / 256, 256>>>(mv, wm, bm, out);
}

// round 8
// speedup vs baseline: 1.7612x; 1.2641x over previous
#include <cuda_runtime.h>
#include <math.h>

#define N_NODES 50000
#define B 64
#define M 32
#define E 128
#define H 8
#define TILE 64
#define WPAD 132   // weight row pad: multiple of 4 -> float4-aligned rows

// scratch (allocation-free rule: __device__ globals)
__device__ float g_wv_accum[B * E];
__device__ float g_att2[B * M * H];

// ---------------------------------------------------------------------------
// K0: zero accumulator + att2[b][m][h] = mv[b,m,:]@Wa2 + ba2
//     one warp per (b,m); lanes split E (float4 each); shfl reduce.
// ---------------------------------------------------------------------------
__global__ void k0_init(const float* __restrict__ mv,
                        const float* __restrict__ Wa2,
                        const float* __restrict__ ba2) {
    int t = blockIdx.x * blockDim.x + threadIdx.x;
    if (t < B * E) g_wv_accum[t] = 0.f;

    int gwarp = t >> 5;             // (b*M + m), 0..2047
    int lane  = t & 31;
    if (gwarp < B * M) {
        float4 v = ((const float4*)(mv + (size_t)gwarp * E))[lane];
        const float* w0 = Wa2 + (lane * 4) * H;
        float acc[H];
#pragma unroll
        for (int h = 0; h < H; h++)
            acc[h] = v.x * w0[h] + v.y * w0[H + h] + v.z * w0[2 * H + h]
                   + v.w * w0[3 * H + h];
#pragma unroll
        for (int off = 16; off > 0; off >>= 1)
#pragma unroll
            for (int h = 0; h < H; h++)
                acc[h] += __shfl_down_sync(0xffffffffu, acc[h], off);
        if (lane < H) {
            // lane h writes acc[h] gathered via one more shuffle trick:
            // simpler: lane 0 writes all 8
        }
        if (lane == 0) {
#pragma unroll
            for (int h = 0; h < H; h++)
                g_att2[gwarp * H + h] = acc[h] + ba2[h];
        }
    }
}

// ---------------------------------------------------------------------------
// K1: fused per-tile kernel. 64 nodes/block, 256 threads. Exact fp32.
//     2 CTAs/SM (smem 114.9KB x2 fits the 228KB pool).
// ---------------------------------------------------------------------------
__global__ void __launch_bounds__(256, 2)
k1_main(const float* __restrict__ z, const int* __restrict__ batch,
        const float* __restrict__ mv, const float* __restrict__ bias_mask,
        const float* __restrict__ Wv, const float* __restrict__ bv,
        const float* __restrict__ Wo, const float* __restrict__ bo,
        const float* __restrict__ Wa1, const float* __restrict__ ba1,
        const float* __restrict__ Wh, const float* __restrict__ bh,
        float* __restrict__ out) {
    extern __shared__ float sm[];
    float* WT   = sm;                   // [128][WPAD] transposed weight (Wv then Wo)
    float* zs   = WT + 128 * WPAD;      // [64][128] z tile, later output_pre
    float* att1 = zs + TILE * E;        // [64][8]
    float* cofs = att1 + TILE * H;      // [64][32]
    float* Wa1s = cofs + TILE * M;      // [128][8]
    int*   bats = (int*)(Wa1s + E * H); // [64]

    const int tid = threadIdx.x;
    const int tilebase = blockIdx.x * TILE;
    const int nvalid = min(TILE, N_NODES - tilebase);

    // --- cooperative loads ---
    for (int i = tid; i < E * E; i += 256) {          // Wv -> WT (transposed)
        int k = i >> 7, c = i & 127;
        WT[c * WPAD + k] = Wv[i];
    }
    for (int i4 = tid; i4 < TILE * E / 4; i4 += 256) { // z tile (zero-fill tail)
        int n = i4 >> 5;
        float4 v = make_float4(0.f, 0.f, 0.f, 0.f);
        if (n < nvalid) v = ((const float4*)z)[(size_t)(tilebase + n) * 32 + (i4 & 31)];
        ((float4*)zs)[i4] = v;
    }
    for (int i = tid; i < E * H; i += 256) Wa1s[i] = Wa1[i];
    if (tid < TILE) bats[tid] = (tid < nvalid) ? batch[tilebase + tid] : 0;
    __syncthreads();

    // --- att1 = z @ Wa1 + ba1 ---
    for (int p = tid; p < TILE * H; p += 256) {
        int n = p >> 3, h = p & 7;
        float s = 0.f;
        const float* zr = zs + n * E;
#pragma unroll 4
        for (int k = 0; k < E; k++) s += zr[k] * Wa1s[k * H + h];
        att1[p] = s + ba1[h];
    }

    // --- wv GEMM + segment accumulation ---
    const int c  = tid & 127;
    const int nh = tid >> 7;
    const int nb = nh * 32;
    {
        float acc[32];
        float bvc = bv[c];
#pragma unroll
        for (int j = 0; j < 32; j++) acc[j] = bvc;
        for (int k = 0; k < E; k += 4) {
            float4 w4 = *(const float4*)(WT + c * WPAD + k);
#pragma unroll
            for (int j = 0; j < 32; j++) {
                float4 z4 = *(const float4*)(zs + (nb + j) * E + k);
                acc[j] += z4.x * w4.x + z4.y * w4.y + z4.z * w4.z + z4.w * w4.w;
            }
        }
        int curg = -1;
        float run = 0.f;
#pragma unroll
        for (int j = 0; j < 32; j++) {
            int node = nb + j;
            int g = (node < nvalid) ? bats[node] : -2;
            if (g != curg) {
                if (curg >= 0) atomicAdd(&g_wv_accum[curg * E + c], run);
                curg = g;
                run = 0.f;
            }
            if (g >= 0) run += acc[j];
        }
        if (curg >= 0) atomicAdd(&g_wv_accum[curg * E + c], run);
    }
    __syncthreads();

    // --- load Wo -> WT (overwrite) ---
    for (int i = tid; i < E * E; i += 256) {
        int k = i >> 7, cc = i & 127;
        WT[cc * WPAD + k] = Wo[i];
    }

    // --- attention: 4 threads per node ---
    {
        const int nl = tid >> 2, q = tid & 3;
        const int g = bats[nl];
        float a1[H];
#pragma unroll
        for (int h = 0; h < H; h++) a1[h] = att1[nl * H + h];
        float biasv[8];
#pragma unroll
        for (int mi = 0; mi < 8; mi++)
            biasv[mi] = (bias_mask[g * M + q * 8 + mi] - 1.f) * 1e9f;
        float w[8];
        float bh0 = bh[0];
#pragma unroll
        for (int mi = 0; mi < 8; mi++) w[mi] = bh0;
        const float* a2 = g_att2 + g * M * H;
#pragma unroll
        for (int h = 0; h < H; h++) {
            float lh[8];
            float mx = -3.4e38f;
#pragma unroll
            for (int mi = 0; mi < 8; mi++) {
                float l = a1[h] + a2[(q * 8 + mi) * H + h];
                l = (l >= 0.f) ? l : 0.01f * l;   // leaky_relu
                l += biasv[mi];
                lh[mi] = l;
                mx = fmaxf(mx, l);
            }
            mx = fmaxf(mx, __shfl_xor_sync(0xffffffffu, mx, 1));
            mx = fmaxf(mx, __shfl_xor_sync(0xffffffffu, mx, 2));
            float s = 0.f;
#pragma unroll
            for (int mi = 0; mi < 8; mi++) { lh[mi] = __expf(lh[mi] - mx); s += lh[mi]; }
            s += __shfl_xor_sync(0xffffffffu, s, 1);
            s += __shfl_xor_sync(0xffffffffu, s, 2);
            float whh = Wh[h];
            float invs = 1.f / s;
#pragma unroll
            for (int mi = 0; mi < 8; mi++) w[mi] += (lh[mi] * invs) * whh;
        }
        // second softmax over slots
        float mx2 = -3.4e38f;
#pragma unroll
        for (int mi = 0; mi < 8; mi++) mx2 = fmaxf(mx2, w[mi]);
        mx2 = fmaxf(mx2, __shfl_xor_sync(0xffffffffu, mx2, 1));
        mx2 = fmaxf(mx2, __shfl_xor_sync(0xffffffffu, mx2, 2));
        float s2 = 0.f;
#pragma unroll
        for (int mi = 0; mi < 8; mi++) { w[mi] = __expf(w[mi] - mx2); s2 += w[mi]; }
        s2 += __shfl_xor_sync(0xffffffffu, s2, 1);
        s2 += __shfl_xor_sync(0xffffffffu, s2, 2);
        float inv2 = 1.f / s2;
#pragma unroll
        for (int mi = 0; mi < 8; mi++) cofs[nl * M + q * 8 + mi] = w[mi] * inv2;
        __syncwarp();

        // output_pre = coefs @ mv[g]  (this thread owns e-chunk q*32..q*32+31)
        float op[32];
#pragma unroll
        for (int i = 0; i < 32; i++) op[i] = 0.f;
        const float4* mvg = (const float4*)(mv + (size_t)g * M * E) + q * 8;
#pragma unroll 4
        for (int m = 0; m < M; m++) {
            float cm = cofs[nl * M + m];
            const float4* row = mvg + m * 32;
#pragma unroll
            for (int i = 0; i < 8; i++) {
                float4 v = row[i];
                op[i * 4 + 0] += cm * v.x;
                op[i * 4 + 1] += cm * v.y;
                op[i * 4 + 2] += cm * v.z;
                op[i * 4 + 3] += cm * v.w;
            }
        }
        float4* zr = (float4*)(zs + nl * E + q * 32);
#pragma unroll
        for (int i = 0; i < 8; i++)
            zr[i] = make_float4(op[i * 4], op[i * 4 + 1], op[i * 4 + 2], op[i * 4 + 3]);
    }
    __syncthreads();

    // --- out = output_pre @ Wo + bo ---
    {
        float acc2[32];
        float boc = bo[c];
#pragma unroll
        for (int j = 0; j < 32; j++) acc2[j] = boc;
        for (int k = 0; k < E; k += 4) {
            float4 w4 = *(const float4*)(WT + c * WPAD + k);
#pragma unroll
            for (int j = 0; j < 32; j++) {
                float4 z4 = *(const float4*)(zs + (nb + j) * E + k);
                acc2[j] += z4.x * w4.x + z4.y * w4.y + z4.z * w4.z + z4.w * w4.w;
            }
        }
#pragma unroll
        for (int j = 0; j < 32; j++) {
            if (nb + j < nvalid)
                out[(size_t)(tilebase + nb + j) * E + c] = acc2[j];
        }
    }
}

// ---------------------------------------------------------------------------
// K2: state updates + arange output
// out layout: [output N*E | arange N | new_mv B*M*E | new_write_mask | new_bias_mask]
// ---------------------------------------------------------------------------
__global__ void k2_final(const float* __restrict__ mv,
                         const float* __restrict__ write_mask,
                         const float* __restrict__ bias_mask,
                         float* __restrict__ out) {
    int idx = blockIdx.x * blockDim.x + threadIdx.x;
    const size_t OUT1 = (size_t)N_NODES * E;
    const size_t OUT2 = OUT1 + N_NODES;
    const size_t OUT3 = OUT2 + (size_t)B * M * E;
    const size_t OUT4 = OUT3 + (size_t)B * M;
    if (idx < B * M * E) {
        int b = idx >> 12;
        int m = (idx >> 7) & 31;
        float wvv = tanhf(g_wv_accum[b * E + (idx & 127)]);
        out[OUT2 + idx] = mv[idx] + wvv * write_mask[b * M + m];
    }
    if (idx < B * M) {
        int b = idx >> 5, m = idx & 31;
        out[OUT3 + idx] = write_mask[b * M + ((m + 31) & 31)];        // roll(+1)
        out[OUT4 + idx] = fminf(bias_mask[idx] + write_mask[idx], 1.f);
    }
    if (idx < N_NODES) out[OUT1 + idx] = (float)idx;                  // arange
}

// ---------------------------------------------------------------------------
extern "C" void kernel_launch(void* const* d_in, const int* in_sizes, int n_in,
                              void* d_out, int out_size) {
    const float* z     = (const float*)d_in[0];
    const int*   batch = (const int*)d_in[1];
    const float* mv    = (const float*)d_in[2];
    const float* wm    = (const float*)d_in[3];
    const float* bm    = (const float*)d_in[4];
    const float* Wv    = (const float*)d_in[5];
    const float* bv    = (const float*)d_in[6];
    const float* Wo    = (const float*)d_in[7];
    const float* bo    = (const float*)d_in[8];
    const float* Wa1   = (const float*)d_in[9];
    const float* ba1   = (const float*)d_in[10];
    const float* Wa2   = (const float*)d_in[11];
    const float* ba2   = (const float*)d_in[12];
    const float* Wh    = (const float*)d_in[13];
    const float* bh    = (const float*)d_in[14];
    float* out = (float*)d_out;

    const int SMEM_BYTES =
        (128 * WPAD + TILE * E + TILE * H + TILE * M + E * H + TILE) * 4;
    cudaFuncSetAttribute(k1_main, cudaFuncAttributeMaxDynamicSharedMemorySize,
                         SMEM_BYTES);

    // 2048 warps: one per (b,m)
    k0_init<<<(B * M * 32 + 255) / 256, 256>>>(mv, Wa2, ba2);

    int nblocks = (N_NODES + TILE - 1) / TILE;
    k1_main<<<nblocks, 256, SMEM_BYTES>>>(z, batch, mv, bm, Wv, bv, Wo, bo,
                                          Wa1, ba1, Wh, bh, out);

    k2_final<<<(B * M * E + 255) / 256, 256>>>(mv, wm, bm, out);
}

// round 9
// speedup vs baseline: 1.7971x; 1.0204x over previous
#include <cuda_runtime.h>
#include <math.h>

#define N_NODES 50000
#define B 64
#define M 32
#define E 128
#define H 8
#define TILE 64

// scratch (allocation-free rule: __device__ globals)
__device__ float g_wv_accum[B * E];
__device__ float g_att2[B * M * H];

// ---------------------------------------------------------------------------
// K0: one block per graph. att2[b][m][h] = mv[b,m,:]@Wa2 + ba2
// ---------------------------------------------------------------------------
__global__ void k0_init(const float* __restrict__ mv,
                        const float* __restrict__ Wa2,
                        const float* __restrict__ ba2) {
    __shared__ float wa2s[E * H];
    int b = blockIdx.x;
    int t = threadIdx.x;
    for (int i = t; i < E * H; i += 256) wa2s[i] = Wa2[i];
    if (t < E) g_wv_accum[b * E + t] = 0.f;
    __syncthreads();

    int m = t >> 3, h = t & 7;
    const float4* row = (const float4*)(mv + (size_t)(b * M + m) * E);
    float s = 0.f;
#pragma unroll 8
    for (int e4 = 0; e4 < 32; e4++) {
        float4 r = row[e4];
        const float* w = wa2s + e4 * 4 * H + h;
        s += r.x * w[0] + r.y * w[H] + r.z * w[2 * H] + r.w * w[3 * H];
    }
    g_att2[(b * M + m) * H + h] = s + ba2[h];
}

// ---------------------------------------------------------------------------
// K1: fused per-tile kernel. 64 nodes/block, 256 threads, 2 CTAs/SM.
//     GEMM thread tile: 8 nodes x 4 cols (12 LDS.128 per 128 FFMA).
// ---------------------------------------------------------------------------
__global__ void __launch_bounds__(256, 2)
k1_main(const float* __restrict__ z, const int* __restrict__ batch,
        const float* __restrict__ mv, const float* __restrict__ bias_mask,
        const float* __restrict__ Wv, const float* __restrict__ bv,
        const float* __restrict__ Wo, const float* __restrict__ bo,
        const float* __restrict__ Wa1, const float* __restrict__ ba1,
        const float* __restrict__ Wh, const float* __restrict__ bh,
        float* __restrict__ out) {
    extern __shared__ float sm[];
    float* Ws    = sm;                    // [128][128] weight, natural [k][c] (Wv then Wo)
    float* zs    = Ws + E * E;            // [64][128] z tile, later output_pre
    float* att1  = zs + TILE * E;         // [64][8]
    float* cofs  = att1 + TILE * H;       // [64][32]
    float* Wa1T  = cofs + TILE * M;       // [8][128] transposed Wa1
    int*   bats  = (int*)(Wa1T + H * E);  // [64]

    const int tid = threadIdx.x;
    const int tilebase = blockIdx.x * TILE;
    const int nvalid = min(TILE, N_NODES - tilebase);

    // --- cooperative loads ---
    {   // Wv natural layout: straight float4 copy (coalesced)
        const float4* src = (const float4*)Wv;
        float4* dst = (float4*)Ws;
        for (int i = tid; i < E * E / 4; i += 256) dst[i] = src[i];
    }
    for (int i4 = tid; i4 < TILE * E / 4; i4 += 256) { // z tile (zero-fill tail)
        int n = i4 >> 5;
        float4 v = make_float4(0.f, 0.f, 0.f, 0.f);
        if (n < nvalid) v = ((const float4*)z)[(size_t)(tilebase + n) * 32 + (i4 & 31)];
        ((float4*)zs)[i4] = v;
    }
    for (int i = tid; i < E * H; i += 256) {           // Wa1T[h][k] = Wa1[k][h]
        int h = i >> 7, k = i & 127;
        Wa1T[h * E + k] = Wa1[k * H + h];
    }
    if (tid < TILE) bats[tid] = (tid < nvalid) ? batch[tilebase + tid] : 0;
    __syncthreads();

    // --- att1 = z @ Wa1 + ba1 (float4 dots against Wa1T rows) ---
    for (int p = tid; p < TILE * H; p += 256) {
        int n = p >> 3, h = p & 7;
        const float4* zr = (const float4*)(zs + n * E);
        const float4* wr = (const float4*)(Wa1T + h * E);
        float s = 0.f;
#pragma unroll 8
        for (int k4 = 0; k4 < 32; k4++) {
            float4 a = zr[k4], w = wr[k4];
            s += a.x * w.x + a.y * w.y + a.z * w.z + a.w * w.w;
        }
        att1[p] = s + ba1[h];
    }

    // thread tile mapping for GEMMs
    const int cg = tid & 31;        // col group: cols 4*cg .. 4*cg+3
    const int nb = (tid >> 5) * 8;  // node base: 8 nodes

    // --- wv GEMM (8x4 tile) + segment accumulation ---
    {
        float acc[8][4];
        float4 bv4 = ((const float4*)bv)[cg];
#pragma unroll
        for (int j = 0; j < 8; j++) {
            acc[j][0] = bv4.x; acc[j][1] = bv4.y; acc[j][2] = bv4.z; acc[j][3] = bv4.w;
        }
        for (int kq = 0; kq < 32; kq++) {
            const float4* wrow = (const float4*)(Ws + kq * 4 * E) + cg;
            float4 w0 = wrow[0];
            float4 w1 = wrow[32];
            float4 w2 = wrow[64];
            float4 w3 = wrow[96];
#pragma unroll
            for (int j = 0; j < 8; j++) {
                float4 zv = ((const float4*)(zs + (nb + j) * E))[kq];
                acc[j][0] += zv.x * w0.x + zv.y * w1.x + zv.z * w2.x + zv.w * w3.x;
                acc[j][1] += zv.x * w0.y + zv.y * w1.y + zv.z * w2.y + zv.w * w3.y;
                acc[j][2] += zv.x * w0.z + zv.y * w1.z + zv.z * w2.z + zv.w * w3.z;
                acc[j][3] += zv.x * w0.w + zv.y * w1.w + zv.z * w2.w + zv.w * w3.w;
            }
        }
        // run-length segment sum over the 8 nodes
        int curg = -1;
        float run[4] = {0.f, 0.f, 0.f, 0.f};
#pragma unroll
        for (int j = 0; j < 8; j++) {
            int node = nb + j;
            int g = (node < nvalid) ? bats[node] : -2;
            if (g != curg) {
                if (curg >= 0) {
#pragma unroll
                    for (int i = 0; i < 4; i++)
                        atomicAdd(&g_wv_accum[curg * E + 4 * cg + i], run[i]);
                }
                curg = g;
                run[0] = run[1] = run[2] = run[3] = 0.f;
            }
            if (g >= 0) {
#pragma unroll
                for (int i = 0; i < 4; i++) run[i] += acc[j][i];
            }
        }
        if (curg >= 0) {
#pragma unroll
            for (int i = 0; i < 4; i++)
                atomicAdd(&g_wv_accum[curg * E + 4 * cg + i], run[i]);
        }
    }
    __syncthreads();

    // --- load Wo -> Ws (overwrite) + attention phase ---
    {
        const float4* src = (const float4*)Wo;
        float4* dst = (float4*)Ws;
        for (int i = tid; i < E * E / 4; i += 256) dst[i] = src[i];
    }

    // --- attention: 4 threads per node ---
    {
        const int nl = tid >> 2, q = tid & 3;
        const int g = bats[nl];
        float a1[H];
#pragma unroll
        for (int h = 0; h < H; h++) a1[h] = att1[nl * H + h];
        float biasv[8];
#pragma unroll
        for (int mi = 0; mi < 8; mi++)
            biasv[mi] = (bias_mask[g * M + q * 8 + mi] - 1.f) * 1e9f;
        float w[8];
        float bh0 = bh[0];
#pragma unroll
        for (int mi = 0; mi < 8; mi++) w[mi] = bh0;
        const float* a2 = g_att2 + g * M * H;
#pragma unroll
        for (int h = 0; h < H; h++) {
            float lh[8];
            float mx = -3.4e38f;
#pragma unroll
            for (int mi = 0; mi < 8; mi++) {
                float l = a1[h] + a2[(q * 8 + mi) * H + h];
                l = (l >= 0.f) ? l : 0.01f * l;   // leaky_relu
                l += biasv[mi];
                lh[mi] = l;
                mx = fmaxf(mx, l);
            }
            mx = fmaxf(mx, __shfl_xor_sync(0xffffffffu, mx, 1));
            mx = fmaxf(mx, __shfl_xor_sync(0xffffffffu, mx, 2));
            float s = 0.f;
#pragma unroll
            for (int mi = 0; mi < 8; mi++) { lh[mi] = __expf(lh[mi] - mx); s += lh[mi]; }
            s += __shfl_xor_sync(0xffffffffu, s, 1);
            s += __shfl_xor_sync(0xffffffffu, s, 2);
            float whh = Wh[h];
            float invs = 1.f / s;
#pragma unroll
            for (int mi = 0; mi < 8; mi++) w[mi] += (lh[mi] * invs) * whh;
        }
        // second softmax over slots
        float mx2 = -3.4e38f;
#pragma unroll
        for (int mi = 0; mi < 8; mi++) mx2 = fmaxf(mx2, w[mi]);
        mx2 = fmaxf(mx2, __shfl_xor_sync(0xffffffffu, mx2, 1));
        mx2 = fmaxf(mx2, __shfl_xor_sync(0xffffffffu, mx2, 2));
        float s2 = 0.f;
#pragma unroll
        for (int mi = 0; mi < 8; mi++) { w[mi] = __expf(w[mi] - mx2); s2 += w[mi]; }
        s2 += __shfl_xor_sync(0xffffffffu, s2, 1);
        s2 += __shfl_xor_sync(0xffffffffu, s2, 2);
        float inv2 = 1.f / s2;
#pragma unroll
        for (int mi = 0; mi < 8; mi++) cofs[nl * M + q * 8 + mi] = w[mi] * inv2;
        __syncwarp();

        // output_pre = coefs @ mv[g]  (this thread owns e-chunk q*32..q*32+31)
        float op[32];
#pragma unroll
        for (int i = 0; i < 32; i++) op[i] = 0.f;
        const float4* mvg = (const float4*)(mv + (size_t)g * M * E) + q * 8;
#pragma unroll 4
        for (int m = 0; m < M; m++) {
            float cm = cofs[nl * M + m];
            const float4* row = mvg + m * 32;
#pragma unroll
            for (int i = 0; i < 8; i++) {
                float4 v = row[i];
                op[i * 4 + 0] += cm * v.x;
                op[i * 4 + 1] += cm * v.y;
                op[i * 4 + 2] += cm * v.z;
                op[i * 4 + 3] += cm * v.w;
            }
        }
        float4* zr = (float4*)(zs + nl * E + q * 32);
#pragma unroll
        for (int i = 0; i < 8; i++)
            zr[i] = make_float4(op[i * 4], op[i * 4 + 1], op[i * 4 + 2], op[i * 4 + 3]);
    }
    __syncthreads();

    // --- out = output_pre @ Wo + bo (8x4 tile, float4 store) ---
    {
        float acc[8][4];
        float4 bo4 = ((const float4*)bo)[cg];
#pragma unroll
        for (int j = 0; j < 8; j++) {
            acc[j][0] = bo4.x; acc[j][1] = bo4.y; acc[j][2] = bo4.z; acc[j][3] = bo4.w;
        }
        for (int kq = 0; kq < 32; kq++) {
            const float4* wrow = (const float4*)(Ws + kq * 4 * E) + cg;
            float4 w0 = wrow[0];
            float4 w1 = wrow[32];
            float4 w2 = wrow[64];
            float4 w3 = wrow[96];
#pragma unroll
            for (int j = 0; j < 8; j++) {
                float4 zv = ((const float4*)(zs + (nb + j) * E))[kq];
                acc[j][0] += zv.x * w0.x + zv.y * w1.x + zv.z * w2.x + zv.w * w3.x;
                acc[j][1] += zv.x * w0.y + zv.y * w1.y + zv.z * w2.y + zv.w * w3.y;
                acc[j][2] += zv.x * w0.z + zv.y * w1.z + zv.z * w2.z + zv.w * w3.z;
                acc[j][3] += zv.x * w0.w + zv.y * w1.w + zv.z * w2.w + zv.w * w3.w;
            }
        }
#pragma unroll
        for (int j = 0; j < 8; j++) {
            if (nb + j < nvalid)
                ((float4*)(out + (size_t)(tilebase + nb + j) * E))[cg] =
                    make_float4(acc[j][0], acc[j][1], acc[j][2], acc[j][3]);
        }
    }
}

// ---------------------------------------------------------------------------
// K2: state updates + arange output
// out layout: [output N*E | arange N | new_mv B*M*E | new_write_mask | new_bias_mask]
// ---------------------------------------------------------------------------
__global__ void k2_final(const float* __restrict__ mv,
                         const float* __restrict__ write_mask,
                         const float* __restrict__ bias_mask,
                         float* __restrict__ out) {
    int idx = blockIdx.x * blockDim.x + threadIdx.x;
    const size_t OUT1 = (size_t)N_NODES * E;
    const size_t OUT2 = OUT1 + N_NODES;
    const size_t OUT3 = OUT2 + (size_t)B * M * E;
    const size_t OUT4 = OUT3 + (size_t)B * M;
    if (idx < B * M * E) {
        int b = idx >> 12;
        int m = (idx >> 7) & 31;
        float wvv = tanhf(g_wv_accum[b * E + (idx & 127)]);
        out[OUT2 + idx] = mv[idx] + wvv * write_mask[b * M + m];
    }
    if (idx < B * M) {
        int b = idx >> 5, m = idx & 31;
        out[OUT3 + idx] = write_mask[b * M + ((m + 31) & 31)];        // roll(+1)
        out[OUT4 + idx] = fminf(bias_mask[idx] + write_mask[idx], 1.f);
    }
    if (idx < N_NODES) out[OUT1 + idx] = (float)idx;                  // arange
}

// ---------------------------------------------------------------------------
extern "C" void kernel_launch(void* const* d_in, const int* in_sizes, int n_in,
                              void* d_out, int out_size) {
    const float* z     = (const float*)d_in[0];
    const int*   batch = (const int*)d_in[1];
    const float* mv    = (const float*)d_in[2];
    const float* wm    = (const float*)d_in[3];
    const float* bm    = (const float*)d_in[4];
    const float* Wv    = (const float*)d_in[5];
    const float* bv    = (const float*)d_in[6];
    const float* Wo    = (const float*)d_in[7];
    const float* bo    = (const float*)d_in[8];
    const float* Wa1   = (const float*)d_in[9];
    const float* ba1   = (const float*)d_in[10];
    const float* Wa2   = (const float*)d_in[11];
    const float* ba2   = (const float*)d_in[12];
    const float* Wh    = (const float*)d_in[13];
    const float* bh    = (const float*)d_in[14];
    float* out = (float*)d_out;

    const int SMEM_BYTES =
        (E * E + TILE * E + TILE * H + TILE * M + H * E + TILE) * 4;
    cudaFuncSetAttribute(k1_main, cudaFuncAttributeMaxDynamicSharedMemorySize,
                         SMEM_BYTES);

    k0_init<<<B, 256>>>(mv, Wa2, ba2);

    int nblocks = (N_NODES + TILE - 1) / TILE;
    k1_main<<<nblocks, 256, SMEM_BYTES>>>(z, batch, mv, bm, Wv, bv, Wo, bo,
                                          Wa1, ba1, Wh, bh, out);

    k2_final<<<(B * M * E + 255) / 256, 256>>>(mv, wm, bm, out);
}